// round 2
// baseline (speedup 1.0000x reference)
#include <cuda_runtime.h>
#include <math.h>

#define N_NODES 50000
#define N_EDGES 400000
#define SLOPE   0.2f

// ---------------- scratch (__device__ globals; no allocation allowed) ----------------
__device__ __align__(16) float g_node_emb[(size_t)N_NODES * 128];
__device__ __align__(16) float g_P[(size_t)N_NODES * 128];          // node_emb @ W_upd[0:128]
__device__ __align__(16) float g_star[N_NODES * 8];                 // node_emb @ W_attn[0:128]
__device__ __align__(16) float g_ssrc[N_NODES * 8];                 // node_emb @ W_attn[384:512]
__device__ __align__(16) float g_attrpart[(size_t)N_EDGES * 128];   // attr_emb @ W_upd[128:256]
__device__ __align__(16) float g_ex[N_EDGES * 8];
__device__ __align__(16) float g_denom[N_NODES * 8];
__device__ int   g_src[N_EDGES], g_tar[N_EDGES];
__device__ int   g_ntype[N_NODES];
__device__ int   g_deg[N_NODES], g_off[N_NODES + 1], g_cursor[N_NODES], g_perm[N_EDGES];

__device__ __forceinline__ float lrelu(float x) { return x >= 0.f ? x : SLOPE * x; }

// ---------------- init (indices are INT32 — jax x64 disabled) ----------------
__global__ void k_init(const int* __restrict__ eidx, const int* __restrict__ ntl) {
    int i = blockIdx.x * blockDim.x + threadIdx.x;
    if (i < N_EDGES) {
        g_src[i] = eidx[i];
        g_tar[i] = eidx[N_EDGES + i];
    }
    if (i < N_NODES * 8) g_denom[i] = 0.f;
    if (i < N_NODES) { g_deg[i] = 0; g_ntype[i] = ntl[i]; }
}

__global__ void k_hist() {
    int i = blockIdx.x * blockDim.x + threadIdx.x;
    if (i < N_EDGES) atomicAdd(&g_deg[g_src[i]], 1);
}

// single-block scan of N_NODES degrees
__global__ void k_scan() {
    __shared__ int s[1024];
    const int CH = (N_NODES + 1023) / 1024;  // 49
    int t = threadIdx.x;
    int base = t * CH;
    int sum = 0;
    for (int i = 0; i < CH; i++) {
        int idx = base + i;
        if (idx < N_NODES) sum += g_deg[idx];
    }
    s[t] = sum;
    __syncthreads();
    for (int d = 1; d < 1024; d <<= 1) {
        int v = (t >= d) ? s[t - d] : 0;
        __syncthreads();
        s[t] += v;
        __syncthreads();
    }
    int run = (t == 0) ? 0 : s[t - 1];
    for (int i = 0; i < CH; i++) {
        int idx = base + i;
        if (idx < N_NODES) {
            g_off[idx] = run;
            g_cursor[idx] = run;
            run += g_deg[idx];
        }
    }
    if (t == 1023) g_off[N_NODES] = N_EDGES;
}

__global__ void k_scatter() {
    int i = blockIdx.x * blockDim.x + threadIdx.x;
    if (i < N_EDGES) {
        int p = atomicAdd(&g_cursor[g_src[i]], 1);
        g_perm[p] = i;
    }
}

// ---------------- node embedding: emb[n] = x[n] @ W_node[type[n]] ----------------
__global__ void k_nodeemb(const float* __restrict__ x, const float* __restrict__ Wn) {
    __shared__ float sx[32 * 256];
    int n0 = blockIdx.x * 32;
    int t = threadIdx.x;
    for (int i = t; i < 32 * 64; i += 256) {   // float4 units
        int row = i >> 6, c4 = i & 63;
        int node = n0 + row;
        float4 v = make_float4(0.f, 0.f, 0.f, 0.f);
        if (node < N_NODES) v = *(const float4*)(x + (size_t)node * 256 + c4 * 4);
        *(float4*)(sx + row * 256 + c4 * 4) = v;
    }
    __syncthreads();
    int tx = t & 31, ty = t >> 5;
    int r0 = ty * 4;
    const float* wp[4];
    int nodes[4];
#pragma unroll
    for (int j = 0; j < 4; j++) {
        int node = n0 + r0 + j;
        nodes[j] = node;
        int tp = (node < N_NODES) ? g_ntype[node] : 0;
        wp[j] = Wn + (size_t)tp * (256 * 128) + tx * 4;
    }
    float acc[4][4];
#pragma unroll
    for (int j = 0; j < 4; j++)
#pragma unroll
        for (int c = 0; c < 4; c++) acc[j][c] = 0.f;
#pragma unroll 4
    for (int k = 0; k < 256; k++) {
#pragma unroll
        for (int j = 0; j < 4; j++) {
            float4 w = *(const float4*)(wp[j] + (size_t)k * 128);
            float xv = sx[(r0 + j) * 256 + k];
            acc[j][0] += xv * w.x;
            acc[j][1] += xv * w.y;
            acc[j][2] += xv * w.z;
            acc[j][3] += xv * w.w;
        }
    }
#pragma unroll
    for (int j = 0; j < 4; j++) {
        if (nodes[j] < N_NODES) {
            *(float4*)(g_node_emb + (size_t)nodes[j] * 128 + tx * 4) =
                make_float4(acc[j][0], acc[j][1], acc[j][2], acc[j][3]);
        }
    }
}

// ---------------- per-node projections: P, s_tar, s_src ----------------
__global__ void k_nodeproj(const float* __restrict__ Wupd, const float* __restrict__ Wattn) {
    __shared__ float se[32 * 132];
    int n0 = blockIdx.x * 32;
    int t = threadIdx.x;
    for (int i = t; i < 32 * 32; i += 256) {   // float4 units
        int row = i >> 5, c4 = i & 31;
        int node = n0 + row;
        float4 v = make_float4(0.f, 0.f, 0.f, 0.f);
        if (node < N_NODES) v = *(const float4*)(g_node_emb + (size_t)node * 128 + c4 * 4);
        *(float4*)(se + row * 132 + c4 * 4) = v;
    }
    __syncthreads();
    // P = emb @ W_upd[0:128]
    int tx = t & 31, ty = t >> 5;
    int r0 = ty * 4;
    float acc[4][4];
#pragma unroll
    for (int j = 0; j < 4; j++)
#pragma unroll
        for (int c = 0; c < 4; c++) acc[j][c] = 0.f;
#pragma unroll 4
    for (int k = 0; k < 128; k++) {
        float4 w = *(const float4*)(Wupd + (size_t)k * 128 + tx * 4);
#pragma unroll
        for (int j = 0; j < 4; j++) {
            float xv = se[(r0 + j) * 132 + k];
            acc[j][0] += xv * w.x;
            acc[j][1] += xv * w.y;
            acc[j][2] += xv * w.z;
            acc[j][3] += xv * w.w;
        }
    }
#pragma unroll
    for (int j = 0; j < 4; j++) {
        int node = n0 + r0 + j;
        if (node < N_NODES)
            *(float4*)(g_P + (size_t)node * 128 + tx * 4) =
                make_float4(acc[j][0], acc[j][1], acc[j][2], acc[j][3]);
    }
    // s_tar / s_src : 32 nodes x 8 heads
    int e = t >> 3, h = t & 7;
    int node = n0 + e;
    float at = 0.f, as = 0.f;
    for (int k = 0; k < 128; k++) {
        float v = se[e * 132 + k];
        at += v * Wattn[k * 8 + h];
        as += v * Wattn[(384 + k) * 8 + h];
    }
    if (node < N_NODES) {
        g_star[node * 8 + h] = at;
        g_ssrc[node * 8 + h] = as;
    }
}

// ---------------- fused edge kernel ----------------
// dynamic smem layout (floats): Xa[2048] Xt[2048] A[32*132] T[32*132] Wa[2048] W[8192]
#define SM_XA 0
#define SM_XT 2048
#define SM_A  4096
#define SM_T  8320
#define SM_WA 12544
#define SM_W  14592
#define EDGE_SMEM_FLOATS (14592 + 8192)
#define EDGE_SMEM_BYTES  (EDGE_SMEM_FLOATS * 4)

__global__ void k_edge(const float* __restrict__ eattr, const float* __restrict__ etype,
                       const float* __restrict__ Weattr, const float* __restrict__ Wetype,
                       const float* __restrict__ Wupd, const float* __restrict__ Wattn) {
    extern __shared__ float sm[];
    __shared__ int sSrc[32], sTar[32];
    float* Xa = sm + SM_XA;
    float* Xt = sm + SM_XT;
    float* A  = sm + SM_A;
    float* T  = sm + SM_T;
    float* Wa = sm + SM_WA;
    float* W  = sm + SM_W;

    int e0 = blockIdx.x * 32;
    int t = threadIdx.x;

    // loads: inputs, W_attn[128:384], W_eattr
    for (int i = t; i < 512; i += 256) {
        ((float4*)Xa)[i] = ((const float4*)(eattr + (size_t)e0 * 64))[i];
        ((float4*)Xt)[i] = ((const float4*)(etype + (size_t)e0 * 64))[i];
        ((float4*)Wa)[i] = ((const float4*)Wattn)[256 + i];
    }
    for (int i = t; i < 2048; i += 256) ((float4*)W)[i] = ((const float4*)Weattr)[i];
    if (t < 32) { sSrc[t] = g_src[e0 + t]; sTar[t] = g_tar[e0 + t]; }
    __syncthreads();

    int tx = t & 31, ty = t >> 5;
    int r0 = ty * 4;

    // phase A: A = lrelu(Xa @ W_eattr)
    {
        float acc[4][4];
#pragma unroll
        for (int j = 0; j < 4; j++)
#pragma unroll
            for (int c = 0; c < 4; c++) acc[j][c] = 0.f;
#pragma unroll 4
        for (int k = 0; k < 64; k++) {
            float4 w = *(const float4*)(W + k * 128 + tx * 4);
#pragma unroll
            for (int j = 0; j < 4; j++) {
                float xv = Xa[(r0 + j) * 64 + k];
                acc[j][0] += xv * w.x; acc[j][1] += xv * w.y;
                acc[j][2] += xv * w.z; acc[j][3] += xv * w.w;
            }
        }
#pragma unroll
        for (int j = 0; j < 4; j++)
            *(float4*)(A + (r0 + j) * 132 + tx * 4) =
                make_float4(lrelu(acc[j][0]), lrelu(acc[j][1]), lrelu(acc[j][2]), lrelu(acc[j][3]));
    }
    __syncthreads();
    for (int i = t; i < 2048; i += 256) ((float4*)W)[i] = ((const float4*)Wetype)[i];
    __syncthreads();

    // phase T: T = lrelu(Xt @ W_etype)
    {
        float acc[4][4];
#pragma unroll
        for (int j = 0; j < 4; j++)
#pragma unroll
            for (int c = 0; c < 4; c++) acc[j][c] = 0.f;
#pragma unroll 4
        for (int k = 0; k < 64; k++) {
            float4 w = *(const float4*)(W + k * 128 + tx * 4);
#pragma unroll
            for (int j = 0; j < 4; j++) {
                float xv = Xt[(r0 + j) * 64 + k];
                acc[j][0] += xv * w.x; acc[j][1] += xv * w.y;
                acc[j][2] += xv * w.z; acc[j][3] += xv * w.w;
            }
        }
#pragma unroll
        for (int j = 0; j < 4; j++)
            *(float4*)(T + (r0 + j) * 132 + tx * 4) =
                make_float4(lrelu(acc[j][0]), lrelu(acc[j][1]), lrelu(acc[j][2]), lrelu(acc[j][3]));
    }
    __syncthreads();

    // attrpart = A @ W_upd[128:256], K split in two 64-row halves of W_upd_bot
    float accP[4][4];
#pragma unroll
    for (int j = 0; j < 4; j++)
#pragma unroll
        for (int c = 0; c < 4; c++) accP[j][c] = 0.f;

    for (int i = t; i < 2048; i += 256) ((float4*)W)[i] = ((const float4*)Wupd)[4096 + i]; // rows 128..191
    __syncthreads();
#pragma unroll 4
    for (int k = 0; k < 64; k++) {
        float4 w = *(const float4*)(W + k * 128 + tx * 4);
#pragma unroll
        for (int j = 0; j < 4; j++) {
            float xv = A[(r0 + j) * 132 + k];
            accP[j][0] += xv * w.x; accP[j][1] += xv * w.y;
            accP[j][2] += xv * w.z; accP[j][3] += xv * w.w;
        }
    }
    __syncthreads();
    for (int i = t; i < 2048; i += 256) ((float4*)W)[i] = ((const float4*)Wupd)[6144 + i]; // rows 192..255
    __syncthreads();
#pragma unroll 4
    for (int k = 0; k < 64; k++) {
        float4 w = *(const float4*)(W + k * 128 + tx * 4);
#pragma unroll
        for (int j = 0; j < 4; j++) {
            float xv = A[(r0 + j) * 132 + 64 + k];
            accP[j][0] += xv * w.x; accP[j][1] += xv * w.y;
            accP[j][2] += xv * w.z; accP[j][3] += xv * w.w;
        }
    }
#pragma unroll
    for (int j = 0; j < 4; j++)
        *(float4*)(g_attrpart + (size_t)(e0 + r0 + j) * 128 + tx * 4) =
            make_float4(accP[j][0], accP[j][1], accP[j][2], accP[j][3]);

    // scores: thread = (edge, head). exp w/o max shift (scores bounded)
    {
        int e = t >> 3, h = t & 7;
        int src = sSrc[e], tar = sTar[e];
        float sc = g_star[tar * 8 + h] + g_ssrc[src * 8 + h];
#pragma unroll 4
        for (int k = 0; k < 128; k++) {
            sc += A[e * 132 + k] * Wa[k * 8 + h];
            sc += T[e * 132 + k] * Wa[(128 + k) * 8 + h];
        }
        sc = lrelu(sc);
        float ex = expf(sc);
        g_ex[(e0 + e) * 8 + h] = ex;
        atomicAdd(&g_denom[src * 8 + h], ex);
    }
}

// ---------------- aggregation ----------------
__global__ void k_aggr(float* __restrict__ out) {
    int n = blockIdx.x;
    int t = threadIdx.x;  // 128 threads = output column
    int s = g_off[n], e_end = g_off[n + 1];
    float p = g_P[(size_t)n * 128 + t];
    float acc[8];
#pragma unroll
    for (int h = 0; h < 8; h++) acc[h] = 0.f;
    if (e_end > s) {
        for (int j = s; j < e_end; j++) {
            int e = g_perm[j];
            float m = lrelu(p + g_attrpart[(size_t)e * 128 + t]);
            const float4* xp = (const float4*)(g_ex + e * 8);
            float4 ea = xp[0], eb = xp[1];
            acc[0] += ea.x * m; acc[1] += ea.y * m; acc[2] += ea.z * m; acc[3] += ea.w * m;
            acc[4] += eb.x * m; acc[5] += eb.y * m; acc[6] += eb.z * m; acc[7] += eb.w * m;
        }
        const float4* dp = (const float4*)(g_denom + n * 8);
        float4 da = dp[0], db = dp[1];
        acc[0] /= da.x; acc[1] /= da.y; acc[2] /= da.z; acc[3] /= da.w;
        acc[4] /= db.x; acc[5] /= db.y; acc[6] /= db.z; acc[7] /= db.w;
    }
#pragma unroll
    for (int h = 0; h < 8; h++) out[(size_t)n * 1024 + h * 128 + t] = acc[h];
}

// ---------------- launch ----------------
extern "C" void kernel_launch(void* const* d_in, const int* in_sizes, int n_in,
                              void* d_out, int out_size) {
    const float* node_feats = (const float*)d_in[0];
    const int*   edge_index = (const int*)d_in[1];    // int32 (jax x64 disabled)
    const float* edge_attr  = (const float*)d_in[2];
    const float* edge_type  = (const float*)d_in[3];
    const int*   ntl        = (const int*)d_in[4];    // int32
    // d_in[5] = edge_type_list (unused by reference)
    const float* W_node  = (const float*)d_in[6];
    const float* W_eattr = (const float*)d_in[7];
    const float* W_etype = (const float*)d_in[8];
    const float* W_upd   = (const float*)d_in[9];
    const float* W_attn  = (const float*)d_in[10];
    float* out = (float*)d_out;

    cudaFuncSetAttribute(k_edge, cudaFuncAttributeMaxDynamicSharedMemorySize, EDGE_SMEM_BYTES);

    const int TB = 256;
    const int GB_E = (N_EDGES + TB - 1) / TB;

    k_init<<<GB_E, TB>>>(edge_index, ntl);
    k_hist<<<GB_E, TB>>>();
    k_scan<<<1, 1024>>>();
    k_scatter<<<GB_E, TB>>>();
    k_nodeemb<<<(N_NODES + 31) / 32, 256>>>(node_feats, W_node);
    k_nodeproj<<<(N_NODES + 31) / 32, 256>>>(W_upd, W_attn);
    k_edge<<<N_EDGES / 32, 256, EDGE_SMEM_BYTES>>>(edge_attr, edge_type, W_eattr, W_etype, W_upd, W_attn);
    k_aggr<<<N_NODES, 128>>>(out);
}